// round 1
// baseline (speedup 1.0000x reference)
#include <cuda_runtime.h>
#include <math.h>

#define NSAMP 64
#define CIN   512
#define TT    64
#define NPAIR 2016

typedef unsigned long long ull;

__device__ __forceinline__ ull pack2(float lo, float hi) {
    ull r;
    asm("mov.b64 %0, {%1, %2};" : "=l"(r) : "f"(lo), "f"(hi));
    return r;
}
__device__ __forceinline__ void unpack2(ull v, float &lo, float &hi) {
    asm("mov.b64 {%0, %1}, %2;" : "=f"(lo), "=f"(hi) : "l"(v));
}
__device__ __forceinline__ ull fma2(ull a, ull b, ull c) {
    ull d;
    asm("fma.rn.f32x2 %0, %1, %2, %3;" : "=l"(d) : "l"(a), "l"(b), "l"(c));
    return d;
}

// Scratch (device globals; no allocation allowed)
__device__ float g_Wall[320 * 512];        // rows 0..255: w_conv1d ; 256..287: A(even) ; 288..319: B(odd)
__device__ float g_biasAll[320];           // matching fused biases
__device__ float g_f[NSAMP * TT * 256];    // [n][t][d]
__device__ float g_a[NSAMP * TT * 32];     // [n][t][o]
__device__ float g_b[NSAMP * TT * 32];     // [n][t][o]

// ---------------------------------------------------------------------------
// prep: build fused weight matrix W_all = [W_conv ; A ; B] and fused biases.
// A[o,c'] = sum_c w_c1[o,2c]   * w_conv1d[c,c']
// B[o,c'] = sum_c w_c1[o,2c+1] * w_conv1d[c,c']
// ---------------------------------------------------------------------------
__global__ void prep_kernel(const float* __restrict__ w_conv1d,
                            const float* __restrict__ b_conv1d,
                            const float* __restrict__ w_c1) {
    int b = blockIdx.x;          // 64 blocks; each owns 8 columns of c'
    int tid = threadIdx.x;       // 256 threads
    int c0 = b * 8;

    // copy w_conv1d rows into g_Wall
    for (int idx = tid; idx < 256 * 8; idx += 256) {
        int row = idx >> 3, cc = c0 + (idx & 7);
        g_Wall[row * 512 + cc] = w_conv1d[row * 512 + cc];
    }
    // fused A/B rows
    for (int idx = tid; idx < 64 * 8; idx += 256) {
        int oa = idx >> 3, cc = c0 + (idx & 7);
        int kind = oa >> 5, o = oa & 31;
        float s = 0.f;
        #pragma unroll 4
        for (int c = 0; c < 256; ++c)
            s += w_c1[o * 512 + 2 * c + kind] * w_conv1d[c * 512 + cc];
        g_Wall[(256 + kind * 32 + o) * 512 + cc] = s;
    }
    if (b == 0) {
        if (tid < 256) g_biasAll[tid] = b_conv1d[tid];
        if (tid < 64) {
            int kind = tid >> 5, o = tid & 31;
            float s = 0.f;
            for (int c = 0; c < 256; ++c)
                s += w_c1[o * 512 + 2 * c + kind] * b_conv1d[c];
            g_biasAll[256 + kind * 32 + o] = s;
        }
    }
}

// ---------------------------------------------------------------------------
// per-sample score head: sigmoid(x_flat . w_mlp + b)
// ---------------------------------------------------------------------------
__global__ void score_kernel(const float* __restrict__ x,
                             const float* __restrict__ w_mlp,
                             const float* __restrict__ b_mlp,
                             float* __restrict__ out) {
    __shared__ float red[256];
    int n = blockIdx.x, tid = threadIdx.x;
    const float4* xv = (const float4*)(x + (size_t)n * CIN * TT);
    const float4* wv = (const float4*)w_mlp;
    float s = 0.f;
    #pragma unroll 4
    for (int i = tid; i < CIN * TT / 4; i += 256) {
        float4 a = xv[i], w = wv[i];
        s += a.x * w.x + a.y * w.y + a.z * w.z + a.w * w.w;
    }
    red[tid] = s;
    __syncthreads();
    for (int off = 128; off > 0; off >>= 1) {
        if (tid < off) red[tid] += red[tid + off];
        __syncthreads();
    }
    if (tid == 0) out[n] = 1.f / (1.f + expf(-(red[0] + b_mlp[0])));
}

// ---------------------------------------------------------------------------
// feat: [f;a;b](n) = W_all(320x512) @ x[n](512x64) + bias
// grid 320 = 64 n  x  5 row-groups of 64 rows. 256 thr = 64 rows x 4 t-quarts.
// ---------------------------------------------------------------------------
__global__ void feat_kernel(const float* __restrict__ x) {
    extern __shared__ float x_sm[];                 // 512*64 floats (128 KB)
    int n = blockIdx.x / 5, rg = blockIdx.x % 5;
    int tid = threadIdx.x;
    int r = tid & 63, tq = tid >> 6;

    const float4* xg = (const float4*)(x + (size_t)n * CIN * TT);
    float4* xs4 = (float4*)x_sm;
    #pragma unroll
    for (int k = 0; k < 32; ++k) xs4[tid + k * 256] = xg[tid + k * 256];
    __syncthreads();

    int row = rg * 64 + r;
    int tb = tq * 16;
    ull acc[8];
    #pragma unroll
    for (int m = 0; m < 8; ++m) acc[m] = 0ULL;

    const float* wr = g_Wall + row * 512;
    #pragma unroll 4
    for (int c = 0; c < 512; ++c) {
        float wv = wr[c];
        ull wp = pack2(wv, wv);
        const ulonglong2* xp = (const ulonglong2*)(x_sm + c * 64 + tb);
        ulonglong2 v0 = xp[0], v1 = xp[1], v2 = xp[2], v3 = xp[3];
        acc[0] = fma2(wp, v0.x, acc[0]);
        acc[1] = fma2(wp, v0.y, acc[1]);
        acc[2] = fma2(wp, v1.x, acc[2]);
        acc[3] = fma2(wp, v1.y, acc[3]);
        acc[4] = fma2(wp, v2.x, acc[4]);
        acc[5] = fma2(wp, v2.y, acc[5]);
        acc[6] = fma2(wp, v3.x, acc[6]);
        acc[7] = fma2(wp, v3.y, acc[7]);
    }
    float bias = g_biasAll[row];
    float vals[16];
    #pragma unroll
    for (int m = 0; m < 8; ++m) {
        float lo, hi; unpack2(acc[m], lo, hi);
        vals[2 * m] = lo + bias; vals[2 * m + 1] = hi + bias;
    }
    if (row < 256) {
        #pragma unroll
        for (int e = 0; e < 16; ++e)
            g_f[(n * TT + tb + e) * 256 + row] = vals[e];
    } else if (row < 288) {
        #pragma unroll
        for (int e = 0; e < 16; ++e)
            g_a[(n * TT + tb + e) * 32 + (row - 256)] = vals[e];
    } else {
        #pragma unroll
        for (int e = 0; e < 16; ++e)
            g_b[(n * TT + tb + e) * 32 + (row - 288)] = vals[e];
    }
}

// ---------------------------------------------------------------------------
// pair: per pair p=(i,j): h[o,hw] = sum_t a_i[o,t] f_j[hw,t] + b_i[o,t] f_j[128+hw,t]
// then pool -> conv2 -> pool -> fc1 -> fc2 -> fc3 -> sigmoid, fully fused.
// 256 thr = 32 o x 8 hw-groups of 16.
// ---------------------------------------------------------------------------
__global__ void pair_kernel(const float* __restrict__ b_c1,
                            const float* __restrict__ w_c2, const float* __restrict__ b_c2,
                            const float* __restrict__ w_fc1, const float* __restrict__ b_fc1,
                            const float* __restrict__ w_fc2, const float* __restrict__ b_fc2,
                            const float* __restrict__ w_fc3, const float* __restrict__ b_fc3,
                            float* __restrict__ out) {
    extern __shared__ float sm[];
    float* f_sm    = sm;             // [64][256] t-major : 16384
    float* a_sm    = sm + 16384;     // [64][32]          : 2048
    float* b_sm    = sm + 18432;     // [64][32]          : 2048
    float* h_sm    = sm + 20480;     // [32][132] padded  : 4224
    float* pool_sm = sm + 24704;     // [32 s][33] padded : 1056
    float* g2_sm   = sm + 25760;     // [8][32]           : 256
    float* v_sm    = sm + 26016;     // 64
    float* v1_sm   = sm + 26080;     // 32
    float* v2_sm   = sm + 26112;     // 8

    int p = blockIdx.x, tid = threadIdx.x;
    int i = 0, rem = p, span = NSAMP - 1;
    while (rem >= span) { rem -= span; --span; ++i; }
    int j = i + 1 + rem;

    const float4* fj = (const float4*)(g_f + (size_t)j * TT * 256);
    float4* fs = (float4*)f_sm;
    #pragma unroll
    for (int k = 0; k < 16; ++k) fs[tid + k * 256] = fj[tid + k * 256];
    const float4* ai = (const float4*)(g_a + (size_t)i * TT * 32);
    ((float4*)a_sm)[tid]       = ai[tid];
    ((float4*)a_sm)[tid + 256] = ai[tid + 256];
    const float4* bi = (const float4*)(g_b + (size_t)i * TT * 32);
    ((float4*)b_sm)[tid]       = bi[tid];
    ((float4*)b_sm)[tid + 256] = bi[tid + 256];
    __syncthreads();

    int o = tid >> 3, g = tid & 7;
    ull acc[8];
    #pragma unroll
    for (int m = 0; m < 8; ++m) acc[m] = 0ULL;

    #pragma unroll 2
    for (int t = 0; t < TT; ++t) {
        float av = a_sm[t * 32 + o];
        float bv = b_sm[t * 32 + o];
        ull ap = pack2(av, av), bp = pack2(bv, bv);
        const ulonglong2* flo = (const ulonglong2*)(f_sm + t * 256 + g * 16);
        const ulonglong2* fhi = (const ulonglong2*)(f_sm + t * 256 + 128 + g * 16);
        ulonglong2 l0 = flo[0], l1 = flo[1], l2 = flo[2], l3 = flo[3];
        ulonglong2 h0 = fhi[0], h1 = fhi[1], h2 = fhi[2], h3 = fhi[3];
        acc[0] = fma2(ap, l0.x, acc[0]); acc[0] = fma2(bp, h0.x, acc[0]);
        acc[1] = fma2(ap, l0.y, acc[1]); acc[1] = fma2(bp, h0.y, acc[1]);
        acc[2] = fma2(ap, l1.x, acc[2]); acc[2] = fma2(bp, h1.x, acc[2]);
        acc[3] = fma2(ap, l1.y, acc[3]); acc[3] = fma2(bp, h1.y, acc[3]);
        acc[4] = fma2(ap, l2.x, acc[4]); acc[4] = fma2(bp, h2.x, acc[4]);
        acc[5] = fma2(ap, l2.y, acc[5]); acc[5] = fma2(bp, h2.y, acc[5]);
        acc[6] = fma2(ap, l3.x, acc[6]); acc[6] = fma2(bp, h3.x, acc[6]);
        acc[7] = fma2(ap, l3.y, acc[7]); acc[7] = fma2(bp, h3.y, acc[7]);
    }
    float bc1 = b_c1[o];
    float* hr = h_sm + o * 132 + g * 16;
    #pragma unroll
    for (int m = 0; m < 8; ++m) {
        float lo, hi; unpack2(acc[m], lo, hi);
        hr[2 * m] = lo + bc1; hr[2 * m + 1] = hi + bc1;
    }
    __syncthreads();

    // maxpool 2x2 over (H=32, W=4): pooled[o, s=ph*2+pw]
    #pragma unroll
    for (int idx = tid; idx < 1024; idx += 256) {
        int oo = idx >> 5, s = idx & 31;
        int ph = s >> 1, pw = s & 1;
        const float* hb = h_sm + oo * 132 + ph * 8 + pw * 2;
        float m0 = fmaxf(hb[0], hb[1]);
        float m1 = fmaxf(hb[4], hb[5]);
        pool_sm[s * 33 + oo] = fmaxf(m0, m1);
    }
    __syncthreads();

    // conv2 1x1: [8][32 spatial]
    {
        int o2 = tid >> 5, s = tid & 31;
        float sum = b_c2[o2];
        const float* wr = w_c2 + o2 * 32;
        #pragma unroll
        for (int oo = 0; oo < 32; ++oo)
            sum += wr[oo] * pool_sm[s * 33 + oo];
        g2_sm[o2 * 32 + s] = sum;
    }
    __syncthreads();

    // maxpool 2x2 over (16,2) -> v[64] with v[o2*8+q]
    if (tid < 64) {
        int o2 = tid >> 3, q = tid & 7;
        const float* gb = g2_sm + o2 * 32 + q * 4;
        v_sm[o2 * 8 + q] = fmaxf(fmaxf(gb[0], gb[1]), fmaxf(gb[2], gb[3]));
    }
    __syncthreads();

    if (tid < 32) {
        float z = b_fc1[tid];
        #pragma unroll
        for (int m = 0; m < 64; ++m) z += w_fc1[tid * 64 + m] * v_sm[m];
        v1_sm[tid] = fmaxf(z, 0.f);
    }
    __syncthreads();
    if (tid < 8) {
        float z = b_fc2[tid];
        #pragma unroll
        for (int m = 0; m < 32; ++m) z += w_fc2[tid * 32 + m] * v1_sm[m];
        v2_sm[tid] = fmaxf(z, 0.f);
    }
    __syncthreads();
    if (tid == 0) {
        float z = b_fc3[0];
        #pragma unroll
        for (int m = 0; m < 8; ++m) z += w_fc3[m] * v2_sm[m];
        out[NSAMP + p] = 1.f / (1.f + expf(-z));
    }
}

extern "C" void kernel_launch(void* const* d_in, const int* in_sizes, int n_in,
                              void* d_out, int out_size) {
    const float* x        = (const float*)d_in[0];
    const float* w_conv1d = (const float*)d_in[1];
    const float* b_conv1d = (const float*)d_in[2];
    const float* w_c1     = (const float*)d_in[3];
    const float* b_c1     = (const float*)d_in[4];
    const float* w_c2     = (const float*)d_in[5];
    const float* b_c2     = (const float*)d_in[6];
    const float* w_fc1    = (const float*)d_in[7];
    const float* b_fc1    = (const float*)d_in[8];
    const float* w_fc2    = (const float*)d_in[9];
    const float* b_fc2    = (const float*)d_in[10];
    const float* w_fc3    = (const float*)d_in[11];
    const float* b_fc3    = (const float*)d_in[12];
    const float* w_mlp    = (const float*)d_in[13];
    const float* b_mlp    = (const float*)d_in[14];
    float* out = (float*)d_out;

    cudaFuncSetAttribute(feat_kernel, cudaFuncAttributeMaxDynamicSharedMemorySize, 512 * 64 * 4);
    cudaFuncSetAttribute(pair_kernel, cudaFuncAttributeMaxDynamicSharedMemorySize, 26120 * 4);

    prep_kernel<<<64, 256>>>(w_conv1d, b_conv1d, w_c1);
    score_kernel<<<64, 256>>>(x, w_mlp, b_mlp, out);
    feat_kernel<<<320, 256, 512 * 64 * 4>>>(x);
    pair_kernel<<<NPAIR, 256, 26120 * 4>>>(b_c1, w_c2, b_c2, w_fc1, b_fc1,
                                           w_fc2, b_fc2, w_fc3, b_fc3, out);
}

// round 2
// speedup vs baseline: 2.7582x; 2.7582x over previous
#include <cuda_runtime.h>
#include <math.h>

#define NSAMP 64
#define CIN   512
#define TT    64
#define NPAIR 2016

typedef unsigned long long ull;

__device__ __forceinline__ ull pack2(float lo, float hi) {
    ull r;
    asm("mov.b64 %0, {%1, %2};" : "=l"(r) : "f"(lo), "f"(hi));
    return r;
}
__device__ __forceinline__ void unpack2(ull v, float &lo, float &hi) {
    asm("mov.b64 {%0, %1}, %2;" : "=f"(lo), "=f"(hi) : "l"(v));
}
__device__ __forceinline__ ull fma2(ull a, ull b, ull c) {
    ull d;
    asm("fma.rn.f32x2 %0, %1, %2, %3;" : "=l"(d) : "l"(a), "l"(b), "l"(c));
    return d;
}

// Scratch (device globals; no allocation allowed)
__device__ __align__(16) float g_Wt[512 * 320];          // transposed: [c][row]; rows 0..255 = w_conv, 256..287 = A, 288..319 = B
__device__ __align__(16) float g_biasAll[320];
__device__ __align__(16) float g_Fe[NSAMP * 128 * 128];  // [n][t'][hw]: t'<64 -> f[hw][t], t'>=64 -> f[128+hw][t-64]
__device__ __align__(16) float g_G [NSAMP * 128 * 32];   // [n][t'][o] : t'<64 -> a[o][t],  t'>=64 -> b[o][t-64]

// ---------------------------------------------------------------------------
// prep: emit transposed W (with fused A/B rows) + fused biases.
// A[o,c'] = sum_c w_c1[o,2c] * w_conv1d[c,c'];  B uses odd taps.
// ---------------------------------------------------------------------------
__global__ void prep_kernel(const float* __restrict__ w_conv1d,
                            const float* __restrict__ b_conv1d,
                            const float* __restrict__ w_c1) {
    extern __shared__ float psm[];
    float* w1_sm = psm;            // 32*512 = 16384
    float* wc_sm = psm + 16384;    // 256*8  = 2048
    int b = blockIdx.x;            // 64 blocks, each owns 8 c' columns
    int tid = threadIdx.x;         // 256 threads
    int c0 = b * 8;

    // stage full w_c1 (64 KB)
    {
        const float4* src = (const float4*)w_c1;
        float4* dst = (float4*)w1_sm;
        #pragma unroll
        for (int k = 0; k < 16; ++k) dst[tid + k * 256] = src[tid + k * 256];
    }
    // stage w_conv columns c0..c0+8 + write transpose for rows 0..255
    for (int idx = tid; idx < 2048; idx += 256) {
        int c = idx >> 3, k = idx & 7;
        float v = w_conv1d[c * 512 + c0 + k];
        wc_sm[idx] = v;
        g_Wt[(c0 + k) * 320 + c] = v;
    }
    __syncthreads();

    // fused A/B rows (rows 256..319 of Wt)
    for (int idx = tid; idx < 512; idx += 256) {
        int ao = idx >> 3, k = idx & 7;
        int kind = ao >> 5, o = ao & 31;
        float s = 0.f;
        #pragma unroll 8
        for (int c = 0; c < 256; ++c)
            s += w1_sm[o * 512 + 2 * c + kind] * wc_sm[c * 8 + k];
        g_Wt[(c0 + k) * 320 + 256 + kind * 32 + o] = s;
    }

    if (b == 0) {
        if (tid < 256) g_biasAll[tid] = b_conv1d[tid];
        if (tid < 64) {
            int kind = tid >> 5, o = tid & 31;
            float s = 0.f;
            for (int c = 0; c < 256; ++c)
                s += w1_sm[o * 512 + 2 * c + kind] * b_conv1d[c];
            g_biasAll[256 + kind * 32 + o] = s;
        }
    }
}

// ---------------------------------------------------------------------------
// per-sample score head
// ---------------------------------------------------------------------------
__global__ void score_kernel(const float* __restrict__ x,
                             const float* __restrict__ w_mlp,
                             const float* __restrict__ b_mlp,
                             float* __restrict__ out) {
    __shared__ float red[256];
    int n = blockIdx.x, tid = threadIdx.x;
    const float4* xv = (const float4*)(x + (size_t)n * CIN * TT);
    const float4* wv = (const float4*)w_mlp;
    float s = 0.f;
    #pragma unroll 4
    for (int i = tid; i < CIN * TT / 4; i += 256) {
        float4 a = xv[i], w = wv[i];
        s += a.x * w.x + a.y * w.y + a.z * w.z + a.w * w.w;
    }
    red[tid] = s;
    __syncthreads();
    for (int off = 128; off > 0; off >>= 1) {
        if (tid < off) red[tid] += red[tid + off];
        __syncthreads();
    }
    if (tid == 0) out[n] = 1.f / (1.f + expf(-(red[0] + b_mlp[0])));
}

// ---------------------------------------------------------------------------
// feat: [Fe;G](n) rows = Wt^T(320x512) @ x[n](512x64) + bias
// grid 320 = 64 n x 5 rowgroups of 64. 256 thr = 16 row-quads x 16 t-quads.
// Thread tile 4 rows x 4 t, fma2.
// ---------------------------------------------------------------------------
__global__ void feat_kernel(const float* __restrict__ x) {
    extern __shared__ float x_sm[];                 // 512*64 floats (128 KB)
    int n = blockIdx.x / 5, rg = blockIdx.x % 5;
    int tid = threadIdx.x;

    const float4* xg = (const float4*)(x + (size_t)n * CIN * TT);
    float4* xs4 = (float4*)x_sm;
    #pragma unroll
    for (int k = 0; k < 32; ++k) xs4[tid + k * 256] = xg[tid + k * 256];
    __syncthreads();

    int rq = tid >> 4, tq = tid & 15;
    int row0 = rg * 64 + rq * 4;
    int t0 = tq * 4;

    ull acc[4][2];
    #pragma unroll
    for (int r = 0; r < 4; ++r) { acc[r][0] = 0ULL; acc[r][1] = 0ULL; }

    #pragma unroll 4
    for (int c = 0; c < 512; ++c) {
        float4 wv = *(const float4*)(g_Wt + c * 320 + row0);
        float4 xv = *(const float4*)(x_sm + c * 64 + t0);
        ull x01 = pack2(xv.x, xv.y), x23 = pack2(xv.z, xv.w);
        float wa[4] = {wv.x, wv.y, wv.z, wv.w};
        #pragma unroll
        for (int r = 0; r < 4; ++r) {
            ull wp = pack2(wa[r], wa[r]);
            acc[r][0] = fma2(wp, x01, acc[r][0]);
            acc[r][1] = fma2(wp, x23, acc[r][1]);
        }
    }

    #pragma unroll
    for (int r = 0; r < 4; ++r) {
        int row = row0 + r;
        float bias = g_biasAll[row];
        float v[4];
        unpack2(acc[r][0], v[0], v[1]);
        unpack2(acc[r][1], v[2], v[3]);
        #pragma unroll
        for (int k = 0; k < 4; ++k) {
            float val = v[k] + bias;
            int t = t0 + k;
            if (row < 256) {
                int d = row;
                int tp = (d < 128) ? t : (64 + t);
                int hw = (d < 128) ? d : (d - 128);
                g_Fe[(size_t)n * 16384 + tp * 128 + hw] = val;
            } else if (row < 288) {
                g_G[(size_t)n * 4096 + t * 32 + (row - 256)] = val;
            } else {
                g_G[(size_t)n * 4096 + (64 + t) * 32 + (row - 288)] = val;
            }
        }
    }
}

// ---------------------------------------------------------------------------
// pair: h(32x128) = G_i^T(32x128K) @ Fe_j(128K x 128hw), K=128 extended.
// 128 thr = 4 o-groups (8 o each) x 32 hw-groups (4 hw each).
// Then fused pool -> conv2 -> pool -> fc1/2/3 -> sigmoid.
// ---------------------------------------------------------------------------
#define PAIR_SMEM_FLOATS 23976

__global__ void pair_kernel(const float* __restrict__ b_c1,
                            const float* __restrict__ w_c2, const float* __restrict__ b_c2,
                            const float* __restrict__ w_fc1, const float* __restrict__ b_fc1,
                            const float* __restrict__ w_fc2, const float* __restrict__ b_fc2,
                            const float* __restrict__ w_fc3, const float* __restrict__ b_fc3,
                            float* __restrict__ out) {
    extern __shared__ float sm[];
    float* fe_sm   = sm;             // [128 t'][128 hw] : 16384
    float* g_sm    = sm + 16384;     // [128 t'][32 o]   : 4096
    float* tmp_sm  = sm + 20480;     // [32 H][65 pad]   : 2080
    float* pool_sm = sm + 22560;     // [32 s][33 pad]   : 1056
    float* g2_sm   = sm + 23616;     // [8][32]          : 256
    float* v_sm    = sm + 23872;     // 64
    float* v1_sm   = sm + 23936;     // 32
    float* v2_sm   = sm + 23968;     // 8

    int p = blockIdx.x, tid = threadIdx.x;
    int i = 0, rem = p, span = NSAMP - 1;
    while (rem >= span) { rem -= span; --span; ++i; }
    int j = i + 1 + rem;

    // stage Fe_j (64KB) and G_i (16KB)
    {
        const float4* fg = (const float4*)(g_Fe + (size_t)j * 16384);
        float4* fs = (float4*)fe_sm;
        #pragma unroll
        for (int k = 0; k < 32; ++k) fs[tid + k * 128] = fg[tid + k * 128];
        const float4* gg = (const float4*)(g_G + (size_t)i * 4096);
        float4* gs = (float4*)g_sm;
        #pragma unroll
        for (int k = 0; k < 8; ++k) gs[tid + k * 128] = gg[tid + k * 128];
    }
    __syncthreads();

    int og = tid >> 5, hg = tid & 31;

    ull acc[8][2];
    #pragma unroll
    for (int o = 0; o < 8; ++o) { acc[o][0] = 0ULL; acc[o][1] = 0ULL; }

    #pragma unroll 2
    for (int t = 0; t < 128; ++t) {
        float4 a0 = *(const float4*)(g_sm + t * 32 + og * 8);
        float4 a1 = *(const float4*)(g_sm + t * 32 + og * 8 + 4);
        float4 fv = *(const float4*)(fe_sm + t * 128 + hg * 4);
        ull f01 = pack2(fv.x, fv.y), f23 = pack2(fv.z, fv.w);
        float av[8] = {a0.x, a0.y, a0.z, a0.w, a1.x, a1.y, a1.z, a1.w};
        #pragma unroll
        for (int o = 0; o < 8; ++o) {
            ull ap = pack2(av[o], av[o]);
            acc[o][0] = fma2(ap, f01, acc[o][0]);
            acc[o][1] = fma2(ap, f23, acc[o][1]);
        }
    }

    // add conv1 bias + maxpool over W pairs in registers; thread owns H=hg
    #pragma unroll
    for (int oo = 0; oo < 8; ++oo) {
        int o = og * 8 + oo;
        float b = b_c1[o];
        float v0, v1, v2, v3;
        unpack2(acc[oo][0], v0, v1);
        unpack2(acc[oo][1], v2, v3);
        tmp_sm[hg * 65 + o * 2 + 0] = fmaxf(v0 + b, v1 + b);
        tmp_sm[hg * 65 + o * 2 + 1] = fmaxf(v2 + b, v3 + b);
    }
    __syncthreads();

    // finish maxpool over H pairs -> pool_sm[s=ph*2+pw][o]
    #pragma unroll
    for (int idx = tid; idx < 1024; idx += 128) {
        int o = idx >> 5, s = idx & 31;
        int ph = s >> 1, pw = s & 1;
        float a = tmp_sm[(2 * ph) * 65 + o * 2 + pw];
        float b = tmp_sm[(2 * ph + 1) * 65 + o * 2 + pw];
        pool_sm[s * 33 + o] = fmaxf(a, b);
    }
    __syncthreads();

    // conv2 1x1: 8 o2 x 32 spatial
    #pragma unroll
    for (int idx = tid; idx < 256; idx += 128) {
        int o2 = idx >> 5, s = idx & 31;
        float sum = b_c2[o2];
        const float* wr = w_c2 + o2 * 32;
        #pragma unroll
        for (int oo = 0; oo < 32; ++oo)
            sum += wr[oo] * pool_sm[s * 33 + oo];
        g2_sm[o2 * 32 + s] = sum;
    }
    __syncthreads();

    // maxpool (16,2) -> v[64]
    if (tid < 64) {
        int o2 = tid >> 3, q = tid & 7;
        const float* gb = g2_sm + o2 * 32 + q * 4;
        v_sm[o2 * 8 + q] = fmaxf(fmaxf(gb[0], gb[1]), fmaxf(gb[2], gb[3]));
    }
    __syncthreads();

    if (tid < 32) {
        float z = b_fc1[tid];
        #pragma unroll
        for (int m = 0; m < 64; ++m) z += w_fc1[tid * 64 + m] * v_sm[m];
        v1_sm[tid] = fmaxf(z, 0.f);
    }
    __syncthreads();
    if (tid < 8) {
        float z = b_fc2[tid];
        #pragma unroll
        for (int m = 0; m < 32; ++m) z += w_fc2[tid * 32 + m] * v1_sm[m];
        v2_sm[tid] = fmaxf(z, 0.f);
    }
    __syncthreads();
    if (tid == 0) {
        float z = b_fc3[0];
        #pragma unroll
        for (int m = 0; m < 8; ++m) z += w_fc3[m] * v2_sm[m];
        out[NSAMP + p] = 1.f / (1.f + expf(-z));
    }
}

extern "C" void kernel_launch(void* const* d_in, const int* in_sizes, int n_in,
                              void* d_out, int out_size) {
    const float* x        = (const float*)d_in[0];
    const float* w_conv1d = (const float*)d_in[1];
    const float* b_conv1d = (const float*)d_in[2];
    const float* w_c1     = (const float*)d_in[3];
    const float* b_c1     = (const float*)d_in[4];
    const float* w_c2     = (const float*)d_in[5];
    const float* b_c2     = (const float*)d_in[6];
    const float* w_fc1    = (const float*)d_in[7];
    const float* b_fc1    = (const float*)d_in[8];
    const float* w_fc2    = (const float*)d_in[9];
    const float* b_fc2    = (const float*)d_in[10];
    const float* w_fc3    = (const float*)d_in[11];
    const float* b_fc3    = (const float*)d_in[12];
    const float* w_mlp    = (const float*)d_in[13];
    const float* b_mlp    = (const float*)d_in[14];
    float* out = (float*)d_out;

    cudaFuncSetAttribute(prep_kernel, cudaFuncAttributeMaxDynamicSharedMemorySize, (16384 + 2048) * 4);
    cudaFuncSetAttribute(feat_kernel, cudaFuncAttributeMaxDynamicSharedMemorySize, 512 * 64 * 4);
    cudaFuncSetAttribute(pair_kernel, cudaFuncAttributeMaxDynamicSharedMemorySize, PAIR_SMEM_FLOATS * 4);

    prep_kernel<<<64, 256, (16384 + 2048) * 4>>>(w_conv1d, b_conv1d, w_c1);
    score_kernel<<<64, 256>>>(x, w_mlp, b_mlp, out);
    feat_kernel<<<320, 256, 512 * 64 * 4>>>(x);
    pair_kernel<<<NPAIR, 128, PAIR_SMEM_FLOATS * 4>>>(b_c1, w_c2, b_c2, w_fc1, b_fc1,
                                                      w_fc2, b_fc2, w_fc3, b_fc3, out);
}

// round 3
// speedup vs baseline: 4.2752x; 1.5500x over previous
#include <cuda_runtime.h>
#include <math.h>

#define NSAMP 64
#define CIN   512
#define TT    64
#define NPAIR 2016
#define PAIR_BLOCKS 528

typedef unsigned long long ull;

__device__ __forceinline__ ull pack2(float lo, float hi) {
    ull r;
    asm("mov.b64 %0, {%1, %2};" : "=l"(r) : "f"(lo), "f"(hi));
    return r;
}
__device__ __forceinline__ void unpack2(ull v, float &lo, float &hi) {
    asm("mov.b64 {%0, %1}, %2;" : "=f"(lo), "=f"(hi) : "l"(v));
}
__device__ __forceinline__ ull fma2(ull a, ull b, ull c) {
    ull d;
    asm("fma.rn.f32x2 %0, %1, %2, %3;" : "=l"(d) : "l"(a), "l"(b), "l"(c));
    return d;
}

// Scratch (device globals; no allocation allowed)
__device__ __align__(16) float g_Wt[512 * 320];          // [c][row]; rows 0..255 = w_conv, 256..287 = A, 288..319 = B
__device__ __align__(16) float g_biasAll[320];
__device__ __align__(16) float g_Fe[NSAMP * 128 * 128];  // [n][t'][hw]
__device__ __align__(16) float g_G [NSAMP * 128 * 32];   // [n][t'][o]

// ---------------------------------------------------------------------------
// prep: transposed fused weights + biases
// ---------------------------------------------------------------------------
__global__ void prep_kernel(const float* __restrict__ w_conv1d,
                            const float* __restrict__ b_conv1d,
                            const float* __restrict__ w_c1) {
    extern __shared__ float psm[];
    float* w1_sm = psm;            // 32*512
    float* wc_sm = psm + 16384;    // 256*8
    int b = blockIdx.x;
    int tid = threadIdx.x;
    int c0 = b * 8;

    {
        const float4* src = (const float4*)w_c1;
        float4* dst = (float4*)w1_sm;
        #pragma unroll
        for (int k = 0; k < 16; ++k) dst[tid + k * 256] = src[tid + k * 256];
    }
    for (int idx = tid; idx < 2048; idx += 256) {
        int c = idx >> 3, k = idx & 7;
        float v = w_conv1d[c * 512 + c0 + k];
        wc_sm[idx] = v;
        g_Wt[(c0 + k) * 320 + c] = v;
    }
    __syncthreads();

    for (int idx = tid; idx < 512; idx += 256) {
        int ao = idx >> 3, k = idx & 7;
        int kind = ao >> 5, o = ao & 31;
        float s = 0.f;
        #pragma unroll 8
        for (int c = 0; c < 256; ++c)
            s += w1_sm[o * 512 + 2 * c + kind] * wc_sm[c * 8 + k];
        g_Wt[(c0 + k) * 320 + 256 + kind * 32 + o] = s;
    }

    if (b == 0) {
        if (tid < 256) g_biasAll[tid] = b_conv1d[tid];
        if (tid < 64) {
            int kind = tid >> 5, o = tid & 31;
            float s = 0.f;
            for (int c = 0; c < 256; ++c)
                s += w1_sm[o * 512 + 2 * c + kind] * b_conv1d[c];
            g_biasAll[256 + kind * 32 + o] = s;
        }
    }
}

// ---------------------------------------------------------------------------
// score head
// ---------------------------------------------------------------------------
__global__ void score_kernel(const float* __restrict__ x,
                             const float* __restrict__ w_mlp,
                             const float* __restrict__ b_mlp,
                             float* __restrict__ out) {
    __shared__ float red[256];
    int n = blockIdx.x, tid = threadIdx.x;
    const float4* xv = (const float4*)(x + (size_t)n * CIN * TT);
    const float4* wv = (const float4*)w_mlp;
    float s = 0.f;
    #pragma unroll 4
    for (int i = tid; i < CIN * TT / 4; i += 256) {
        float4 a = xv[i], w = wv[i];
        s += a.x * w.x + a.y * w.y + a.z * w.z + a.w * w.w;
    }
    red[tid] = s;
    __syncthreads();
    for (int off = 128; off > 0; off >>= 1) {
        if (tid < off) red[tid] += red[tid + off];
        __syncthreads();
    }
    if (tid == 0) out[n] = 1.f / (1.f + expf(-(red[0] + b_mlp[0])));
}

// ---------------------------------------------------------------------------
// feat v2: 128 blocks = (n, t-half). 320 threads, tile 4 rows x 8 t.
// ---------------------------------------------------------------------------
__global__ __launch_bounds__(320) void feat_kernel(const float* __restrict__ x) {
    extern __shared__ float x_sm[];                 // 512 x 32 = 64 KB
    int bx = blockIdx.x;
    int n = bx >> 1, th = bx & 1;
    int tid = threadIdx.x;

    const float4* xg = (const float4*)(x + (size_t)n * CIN * TT);
    float4* xs4 = (float4*)x_sm;
    for (int idx = tid; idx < 4096; idx += 320) {
        int c = idx >> 3, k = idx & 7;
        xs4[idx] = xg[c * 16 + th * 8 + k];
    }
    __syncthreads();

    int rq = tid >> 2, tg = tid & 3;
    int row0 = rq * 4, t0l = tg * 8;

    ull acc[4][4];
    #pragma unroll
    for (int r = 0; r < 4; ++r)
        #pragma unroll
        for (int k = 0; k < 4; ++k) acc[r][k] = 0ULL;

    #pragma unroll 4
    for (int c = 0; c < 512; ++c) {
        float4 w4 = *(const float4*)(g_Wt + c * 320 + row0);
        const ulonglong2* xp = (const ulonglong2*)(x_sm + c * 32 + t0l);
        ulonglong2 xa = xp[0], xb = xp[1];
        float wa[4] = {w4.x, w4.y, w4.z, w4.w};
        #pragma unroll
        for (int r = 0; r < 4; ++r) {
            ull wp = pack2(wa[r], wa[r]);
            acc[r][0] = fma2(wp, xa.x, acc[r][0]);
            acc[r][1] = fma2(wp, xa.y, acc[r][1]);
            acc[r][2] = fma2(wp, xb.x, acc[r][2]);
            acc[r][3] = fma2(wp, xb.y, acc[r][3]);
        }
    }

    #pragma unroll
    for (int r = 0; r < 4; ++r) {
        int row = row0 + r;
        float bias = g_biasAll[row];
        float v[8];
        unpack2(acc[r][0], v[0], v[1]);
        unpack2(acc[r][1], v[2], v[3]);
        unpack2(acc[r][2], v[4], v[5]);
        unpack2(acc[r][3], v[6], v[7]);
        #pragma unroll
        for (int k = 0; k < 8; ++k) {
            float val = v[k] + bias;
            int t = th * 32 + t0l + k;
            if (row < 256) {
                int d = row;
                int tp = (d < 128) ? t : (64 + t);
                int hw = d & 127;
                g_Fe[(size_t)n * 16384 + tp * 128 + hw] = val;
            } else if (row < 288) {
                g_G[(size_t)n * 4096 + t * 32 + (row - 256)] = val;
            } else {
                g_G[(size_t)n * 4096 + (64 + t) * 32 + (row - 288)] = val;
            }
        }
    }
}

// ---------------------------------------------------------------------------
// pair v3: 528 blocks grouped by j (4 i-units each). 256 thr = 4 units x 64.
// Unit tile: thread = 8 o x 8 hw. Fully fused epilogue per unit.
// ---------------------------------------------------------------------------
__global__ __launch_bounds__(256) void pair_kernel(const float* __restrict__ b_c1,
                            const float* __restrict__ w_c2, const float* __restrict__ b_c2,
                            const float* __restrict__ w_fc1, const float* __restrict__ b_fc1,
                            const float* __restrict__ w_fc2, const float* __restrict__ b_fc2,
                            const float* __restrict__ w_fc3, const float* __restrict__ b_fc3,
                            float* __restrict__ out) {
    extern __shared__ float sm[];
    float* fe_sm = sm;                       // [128][128] : 16384 floats

    int tid = threadIdx.x;
    int b = blockIdx.x;
    int j = 1;
    while (b >= ((j + 3) >> 2)) { b -= (j + 3) >> 2; ++j; }
    int i0 = b * 4;

    int u = tid >> 6, t64 = tid & 63;
    int og = t64 >> 4, hg = t64 & 15;
    float* Gu = sm + 16384 + u * 4096;       // [128][32] per unit

    // stage Fe_j (shared) and per-unit G_i
    {
        const float4* fg = (const float4*)(g_Fe + (size_t)j * 16384);
        float4* fs = (float4*)fe_sm;
        #pragma unroll
        for (int k = 0; k < 16; ++k) fs[tid + k * 256] = fg[tid + k * 256];
        int iu = i0 + u; if (iu >= j) iu = j - 1;
        const float4* gg = (const float4*)(g_G + (size_t)iu * 4096);
        float4* gs = (float4*)Gu;
        #pragma unroll
        for (int k = 0; k < 16; ++k) gs[t64 + k * 64] = gg[t64 + k * 64];
    }
    __syncthreads();

    int o0 = og * 8, hw0 = hg * 8;
    ull acc[8][4];
    #pragma unroll
    for (int oo = 0; oo < 8; ++oo)
        #pragma unroll
        for (int k = 0; k < 4; ++k) acc[oo][k] = 0ULL;

    #pragma unroll 2
    for (int t = 0; t < 128; ++t) {
        float4 af0 = *(const float4*)(Gu + t * 32 + o0);
        float4 af1 = *(const float4*)(Gu + t * 32 + o0 + 4);
        const ulonglong2* fp = (const ulonglong2*)(fe_sm + t * 128 + hw0);
        ulonglong2 fA = fp[0], fB = fp[1];
        float av[8] = {af0.x, af0.y, af0.z, af0.w, af1.x, af1.y, af1.z, af1.w};
        #pragma unroll
        for (int oo = 0; oo < 8; ++oo) {
            ull ap = pack2(av[oo], av[oo]);
            acc[oo][0] = fma2(ap, fA.x, acc[oo][0]);
            acc[oo][1] = fma2(ap, fA.y, acc[oo][1]);
            acc[oo][2] = fma2(ap, fB.x, acc[oo][2]);
            acc[oo][3] = fma2(ap, fB.y, acc[oo][3]);
        }
    }

    bool valid = (i0 + u) < j;
    int bar = u + 1;

    // epilogue buffers alias the unit's (now dead) G region
    float* pool = Gu;           // [32 s][33] : 1056
    float* g2   = Gu + 1056;    // [8][32]    : 256
    float* vv   = Gu + 1312;    // 64
    float* v1   = Gu + 1376;    // 32
    float* v2   = Gu + 1408;    // 8

    asm volatile("bar.sync %0, 64;" :: "r"(bar));

    // bias + 2x2 maxpool entirely per-thread: thread owns H rows 2hg, 2hg+1
    #pragma unroll
    for (int oo = 0; oo < 8; ++oo) {
        int o = o0 + oo;
        float bb = b_c1[o];
        float v0, v1f, v2f, v3, v4, v5, v6, v7;
        unpack2(acc[oo][0], v0, v1f);
        unpack2(acc[oo][1], v2f, v3);
        unpack2(acc[oo][2], v4, v5);
        unpack2(acc[oo][3], v6, v7);
        float q0 = fmaxf(fmaxf(v0, v1f), fmaxf(v4, v5)) + bb;  // pw=0
        float q1 = fmaxf(fmaxf(v2f, v3), fmaxf(v6, v7)) + bb;  // pw=1
        pool[(2 * hg + 0) * 33 + o] = q0;
        pool[(2 * hg + 1) * 33 + o] = q1;
    }
    asm volatile("bar.sync %0, 64;" :: "r"(bar));

    // conv2 1x1: 8 o2 x 32 s; 4 outputs/thread
    #pragma unroll
    for (int k = 0; k < 4; ++k) {
        int idx = t64 + k * 64;
        int o2 = idx >> 5, s = idx & 31;
        float sum = b_c2[o2];
        const float* wr = w_c2 + o2 * 32;
        #pragma unroll
        for (int oo = 0; oo < 32; ++oo)
            sum += wr[oo] * pool[s * 33 + oo];
        g2[o2 * 32 + s] = sum;
    }
    asm volatile("bar.sync %0, 64;" :: "r"(bar));

    // maxpool (16,2)->(8,1): v[64]
    {
        int o2 = t64 >> 3, q = t64 & 7;
        const float* gb = g2 + o2 * 32 + q * 4;
        vv[t64] = fmaxf(fmaxf(gb[0], gb[1]), fmaxf(gb[2], gb[3]));
    }
    asm volatile("bar.sync %0, 64;" :: "r"(bar));

    if (t64 < 32) {
        float z = b_fc1[t64];
        #pragma unroll
        for (int m = 0; m < 64; ++m) z += w_fc1[t64 * 64 + m] * vv[m];
        v1[t64] = fmaxf(z, 0.f);
    }
    asm volatile("bar.sync %0, 64;" :: "r"(bar));
    if (t64 < 8) {
        float z = b_fc2[t64];
        #pragma unroll
        for (int m = 0; m < 32; ++m) z += w_fc2[t64 * 32 + m] * v1[m];
        v2[t64] = fmaxf(z, 0.f);
    }
    asm volatile("bar.sync %0, 64;" :: "r"(bar));
    if (t64 == 0 && valid) {
        float z = b_fc3[0];
        #pragma unroll
        for (int m = 0; m < 8; ++m) z += w_fc3[m] * v2[m];
        int i = i0 + u;
        int p = i * (2 * NSAMP - i - 1) / 2 + (j - i - 1);
        out[NSAMP + p] = 1.f / (1.f + expf(-z));
    }
}

extern "C" void kernel_launch(void* const* d_in, const int* in_sizes, int n_in,
                              void* d_out, int out_size) {
    const float* x        = (const float*)d_in[0];
    const float* w_conv1d = (const float*)d_in[1];
    const float* b_conv1d = (const float*)d_in[2];
    const float* w_c1     = (const float*)d_in[3];
    const float* b_c1     = (const float*)d_in[4];
    const float* w_c2     = (const float*)d_in[5];
    const float* b_c2     = (const float*)d_in[6];
    const float* w_fc1    = (const float*)d_in[7];
    const float* b_fc1    = (const float*)d_in[8];
    const float* w_fc2    = (const float*)d_in[9];
    const float* b_fc2    = (const float*)d_in[10];
    const float* w_fc3    = (const float*)d_in[11];
    const float* b_fc3    = (const float*)d_in[12];
    const float* w_mlp    = (const float*)d_in[13];
    const float* b_mlp    = (const float*)d_in[14];
    float* out = (float*)d_out;

    cudaFuncSetAttribute(prep_kernel, cudaFuncAttributeMaxDynamicSharedMemorySize, (16384 + 2048) * 4);
    cudaFuncSetAttribute(feat_kernel, cudaFuncAttributeMaxDynamicSharedMemorySize, 512 * 32 * 4);
    cudaFuncSetAttribute(pair_kernel, cudaFuncAttributeMaxDynamicSharedMemorySize, 32768 * 4);

    prep_kernel<<<64, 256, (16384 + 2048) * 4>>>(w_conv1d, b_conv1d, w_c1);
    score_kernel<<<64, 256>>>(x, w_mlp, b_mlp, out);
    feat_kernel<<<128, 320, 512 * 32 * 4>>>(x);
    pair_kernel<<<PAIR_BLOCKS, 256, 32768 * 4>>>(b_c1, w_c2, b_c2, w_fc1, b_fc1,
                                                 w_fc2, b_fc2, w_fc3, b_fc3, out);
}

// round 4
// speedup vs baseline: 4.4212x; 1.0342x over previous
#include <cuda_runtime.h>
#include <math.h>

#define NSAMP 64
#define CIN   512
#define TT    64
#define NPAIR 2016
#define PAIR_BLOCKS 280
#define PAIR_SMEM_BYTES ((16384 + 8 * 4096) * 4)

typedef unsigned long long ull;

__device__ __forceinline__ ull pack2(float lo, float hi) {
    ull r;
    asm("mov.b64 %0, {%1, %2};" : "=l"(r) : "f"(lo), "f"(hi));
    return r;
}
__device__ __forceinline__ void unpack2(ull v, float &lo, float &hi) {
    asm("mov.b64 {%0, %1}, %2;" : "=f"(lo), "=f"(hi) : "l"(v));
}
__device__ __forceinline__ ull fma2(ull a, ull b, ull c) {
    ull d;
    asm("fma.rn.f32x2 %0, %1, %2, %3;" : "=l"(d) : "l"(a), "l"(b), "l"(c));
    return d;
}

// Scratch (device globals; no allocation allowed)
__device__ __align__(16) float g_Wt[512 * 320];          // [c][row]
__device__ __align__(16) float g_biasAll[320];
__device__ __align__(16) float g_Fe[NSAMP * 128 * 128];  // [n][t'][hw]
__device__ __align__(16) float g_G [NSAMP * 128 * 32];   // [n][t'][o]

// ---------------------------------------------------------------------------
// prep (+ fused per-sample score head): transposed fused weights + biases,
// then block b computes score[b].
// ---------------------------------------------------------------------------
__global__ void prep_kernel(const float* __restrict__ w_conv1d,
                            const float* __restrict__ b_conv1d,
                            const float* __restrict__ w_c1,
                            const float* __restrict__ x,
                            const float* __restrict__ w_mlp,
                            const float* __restrict__ b_mlp,
                            float* __restrict__ out) {
    extern __shared__ float psm[];
    float* w1_sm = psm;            // 32*512
    float* wc_sm = psm + 16384;    // 256*8
    int b = blockIdx.x;
    int tid = threadIdx.x;
    int c0 = b * 8;

    {
        const float4* src = (const float4*)w_c1;
        float4* dst = (float4*)w1_sm;
        #pragma unroll
        for (int k = 0; k < 16; ++k) dst[tid + k * 256] = src[tid + k * 256];
    }
    for (int idx = tid; idx < 2048; idx += 256) {
        int c = idx >> 3, k = idx & 7;
        float v = w_conv1d[c * 512 + c0 + k];
        wc_sm[idx] = v;
        g_Wt[(c0 + k) * 320 + c] = v;
    }
    __syncthreads();

    for (int idx = tid; idx < 512; idx += 256) {
        int ao = idx >> 3, k = idx & 7;
        int kind = ao >> 5, o = ao & 31;
        float s0 = 0.f, s1 = 0.f;
        #pragma unroll 8
        for (int c = 0; c < 256; c += 2) {
            s0 += w1_sm[o * 512 + 2 * c + kind] * wc_sm[c * 8 + k];
            s1 += w1_sm[o * 512 + 2 * (c + 1) + kind] * wc_sm[(c + 1) * 8 + k];
        }
        g_Wt[(c0 + k) * 320 + 256 + kind * 32 + o] = s0 + s1;
    }

    if (b == 0) {
        if (tid < 256) g_biasAll[tid] = b_conv1d[tid];
        if (tid < 64) {
            int kind = tid >> 5, o = tid & 31;
            float s = 0.f;
            for (int c = 0; c < 256; ++c)
                s += w1_sm[o * 512 + 2 * c + kind] * b_conv1d[c];
            g_biasAll[256 + kind * 32 + o] = s;
        }
    }
    __syncthreads();

    // fused score head for sample n = b
    {
        float* red = psm;   // reuse
        const float4* xv = (const float4*)(x + (size_t)b * CIN * TT);
        const float4* wv = (const float4*)w_mlp;
        float s = 0.f;
        #pragma unroll 4
        for (int i = tid; i < CIN * TT / 4; i += 256) {
            float4 a = xv[i], w = wv[i];
            s += a.x * w.x + a.y * w.y + a.z * w.z + a.w * w.w;
        }
        red[tid] = s;
        __syncthreads();
        for (int off = 128; off > 0; off >>= 1) {
            if (tid < off) red[tid] += red[tid + off];
            __syncthreads();
        }
        if (tid == 0) out[b] = 1.f / (1.f + expf(-(red[0] + b_mlp[0])));
    }
}

// ---------------------------------------------------------------------------
// feat: 128 blocks = (n, t-half). 320 threads, tile 4 rows x 8 t.
// Weight loads double-buffered.
// ---------------------------------------------------------------------------
__global__ __launch_bounds__(320) void feat_kernel(const float* __restrict__ x) {
    extern __shared__ float x_sm[];                 // 512 x 32 = 64 KB
    int bx = blockIdx.x;
    int n = bx >> 1, th = bx & 1;
    int tid = threadIdx.x;

    const float4* xg = (const float4*)(x + (size_t)n * CIN * TT);
    float4* xs4 = (float4*)x_sm;
    for (int idx = tid; idx < 4096; idx += 320) {
        int c = idx >> 3, k = idx & 7;
        xs4[idx] = xg[c * 16 + th * 8 + k];
    }
    __syncthreads();

    int rq = tid >> 2, tg = tid & 3;
    int row0 = rq * 4, t0l = tg * 8;

    ull acc[4][4];
    #pragma unroll
    for (int r = 0; r < 4; ++r)
        #pragma unroll
        for (int k = 0; k < 4; ++k) acc[r][k] = 0ULL;

    float4 wcur = *(const float4*)(g_Wt + row0);
    #pragma unroll 4
    for (int c = 0; c < 512; ++c) {
        float4 w4 = wcur;
        if (c < 511) wcur = *(const float4*)(g_Wt + (c + 1) * 320 + row0);
        const ulonglong2* xp = (const ulonglong2*)(x_sm + c * 32 + t0l);
        ulonglong2 xa = xp[0], xb = xp[1];
        float wa[4] = {w4.x, w4.y, w4.z, w4.w};
        #pragma unroll
        for (int r = 0; r < 4; ++r) {
            ull wp = pack2(wa[r], wa[r]);
            acc[r][0] = fma2(wp, xa.x, acc[r][0]);
            acc[r][1] = fma2(wp, xa.y, acc[r][1]);
            acc[r][2] = fma2(wp, xb.x, acc[r][2]);
            acc[r][3] = fma2(wp, xb.y, acc[r][3]);
        }
    }

    #pragma unroll
    for (int r = 0; r < 4; ++r) {
        int row = row0 + r;
        float bias = g_biasAll[row];
        float v[8];
        unpack2(acc[r][0], v[0], v[1]);
        unpack2(acc[r][1], v[2], v[3]);
        unpack2(acc[r][2], v[4], v[5]);
        unpack2(acc[r][3], v[6], v[7]);
        #pragma unroll
        for (int k = 0; k < 8; ++k) {
            float val = v[k] + bias;
            int t = th * 32 + t0l + k;
            if (row < 256) {
                int d = row;
                int tp = (d < 128) ? t : (64 + t);
                int hw = d & 127;
                g_Fe[(size_t)n * 16384 + tp * 128 + hw] = val;
            } else if (row < 288) {
                g_G[(size_t)n * 4096 + t * 32 + (row - 256)] = val;
            } else {
                g_G[(size_t)n * 4096 + (64 + t) * 32 + (row - 288)] = val;
            }
        }
    }
}

// ---------------------------------------------------------------------------
// pair v4: 280 blocks grouped by j, 8 i-units each. 512 thr = 8 units x 64.
// Unit: thread tile 8 o x 8 hw. Fully fused epilogue per unit.
// ---------------------------------------------------------------------------
__global__ __launch_bounds__(512) void pair_kernel(const float* __restrict__ b_c1,
                            const float* __restrict__ w_c2, const float* __restrict__ b_c2,
                            const float* __restrict__ w_fc1, const float* __restrict__ b_fc1,
                            const float* __restrict__ w_fc2, const float* __restrict__ b_fc2,
                            const float* __restrict__ w_fc3, const float* __restrict__ b_fc3,
                            float* __restrict__ out) {
    extern __shared__ float sm[];
    float* fe_sm = sm;                       // [128][128] : 16384 floats

    int tid = threadIdx.x;
    int b = blockIdx.x;
    int j = 1;
    while (b >= ((j + 7) >> 3)) { b -= (j + 7) >> 3; ++j; }
    int i0 = b * 8;

    int u = tid >> 6, t64 = tid & 63;
    int og = t64 >> 4, hg = t64 & 15;
    float* Gu = sm + 16384 + u * 4096;       // [128][32] per unit

    // stage Fe_j (shared by 8 units) and per-unit G_i
    {
        const float4* fg = (const float4*)(g_Fe + (size_t)j * 16384);
        float4* fs = (float4*)fe_sm;
        #pragma unroll
        for (int k = 0; k < 8; ++k) fs[tid + k * 512] = fg[tid + k * 512];
        int iu = i0 + u; if (iu >= j) iu = j - 1;
        const float4* gg = (const float4*)(g_G + (size_t)iu * 4096);
        float4* gs = (float4*)Gu;
        #pragma unroll
        for (int k = 0; k < 16; ++k) gs[t64 + k * 64] = gg[t64 + k * 64];
    }
    __syncthreads();

    int o0 = og * 8, hw0 = hg * 8;
    ull acc[8][4];
    #pragma unroll
    for (int oo = 0; oo < 8; ++oo)
        #pragma unroll
        for (int k = 0; k < 4; ++k) acc[oo][k] = 0ULL;

    #pragma unroll 2
    for (int t = 0; t < 128; ++t) {
        float4 af0 = *(const float4*)(Gu + t * 32 + o0);
        float4 af1 = *(const float4*)(Gu + t * 32 + o0 + 4);
        const ulonglong2* fp = (const ulonglong2*)(fe_sm + t * 128 + hw0);
        ulonglong2 fA = fp[0], fB = fp[1];
        float av[8] = {af0.x, af0.y, af0.z, af0.w, af1.x, af1.y, af1.z, af1.w};
        #pragma unroll
        for (int oo = 0; oo < 8; ++oo) {
            ull ap = pack2(av[oo], av[oo]);
            acc[oo][0] = fma2(ap, fA.x, acc[oo][0]);
            acc[oo][1] = fma2(ap, fA.y, acc[oo][1]);
            acc[oo][2] = fma2(ap, fB.x, acc[oo][2]);
            acc[oo][3] = fma2(ap, fB.y, acc[oo][3]);
        }
    }

    bool valid = (i0 + u) < j;
    int bar = u + 1;

    // epilogue buffers alias the unit's (now dead) G region
    float* pool = Gu;           // [32 s][33] : 1056
    float* g2   = Gu + 1056;    // [8][32]    : 256
    float* vv   = Gu + 1312;    // 64
    float* v1   = Gu + 1376;    // 32
    float* v2   = Gu + 1408;    // 8

    asm volatile("bar.sync %0, 64;" :: "r"(bar));

    // bias + 2x2 maxpool per-thread: thread owns H rows 2hg, 2hg+1
    #pragma unroll
    for (int oo = 0; oo < 8; ++oo) {
        int o = o0 + oo;
        float bb = b_c1[o];
        float v0, v1f, v2f, v3, v4, v5, v6, v7;
        unpack2(acc[oo][0], v0, v1f);
        unpack2(acc[oo][1], v2f, v3);
        unpack2(acc[oo][2], v4, v5);
        unpack2(acc[oo][3], v6, v7);
        float q0 = fmaxf(fmaxf(v0, v1f), fmaxf(v4, v5)) + bb;
        float q1 = fmaxf(fmaxf(v2f, v3), fmaxf(v6, v7)) + bb;
        pool[(2 * hg + 0) * 33 + o] = q0;
        pool[(2 * hg + 1) * 33 + o] = q1;
    }
    asm volatile("bar.sync %0, 64;" :: "r"(bar));

    // conv2 1x1: 8 o2 x 32 s
    #pragma unroll
    for (int k = 0; k < 4; ++k) {
        int idx = t64 + k * 64;
        int o2 = idx >> 5, s = idx & 31;
        float sum = b_c2[o2];
        const float* wr = w_c2 + o2 * 32;
        #pragma unroll
        for (int oo = 0; oo < 32; ++oo)
            sum += wr[oo] * pool[s * 33 + oo];
        g2[o2 * 32 + s] = sum;
    }
    asm volatile("bar.sync %0, 64;" :: "r"(bar));

    // maxpool (16,2)->(8,1): v[64]
    {
        int o2 = t64 >> 3, q = t64 & 7;
        const float* gb = g2 + o2 * 32 + q * 4;
        vv[t64] = fmaxf(fmaxf(gb[0], gb[1]), fmaxf(gb[2], gb[3]));
    }
    asm volatile("bar.sync %0, 64;" :: "r"(bar));

    if (t64 < 32) {
        float z = b_fc1[t64];
        #pragma unroll
        for (int m = 0; m < 64; ++m) z += w_fc1[t64 * 64 + m] * vv[m];
        v1[t64] = fmaxf(z, 0.f);
    }
    asm volatile("bar.sync %0, 64;" :: "r"(bar));
    if (t64 < 8) {
        float z = b_fc2[t64];
        #pragma unroll
        for (int m = 0; m < 32; ++m) z += w_fc2[t64 * 32 + m] * v1[m];
        v2[t64] = fmaxf(z, 0.f);
    }
    asm volatile("bar.sync %0, 64;" :: "r"(bar));
    if (t64 == 0 && valid) {
        float z = b_fc3[0];
        #pragma unroll
        for (int m = 0; m < 8; ++m) z += w_fc3[m] * v2[m];
        int i = i0 + u;
        int p = i * (2 * NSAMP - i - 1) / 2 + (j - i - 1);
        out[NSAMP + p] = 1.f / (1.f + expf(-z));
    }
}

extern "C" void kernel_launch(void* const* d_in, const int* in_sizes, int n_in,
                              void* d_out, int out_size) {
    const float* x        = (const float*)d_in[0];
    const float* w_conv1d = (const float*)d_in[1];
    const float* b_conv1d = (const float*)d_in[2];
    const float* w_c1     = (const float*)d_in[3];
    const float* b_c1     = (const float*)d_in[4];
    const float* w_c2     = (const float*)d_in[5];
    const float* b_c2     = (const float*)d_in[6];
    const float* w_fc1    = (const float*)d_in[7];
    const float* b_fc1    = (const float*)d_in[8];
    const float* w_fc2    = (const float*)d_in[9];
    const float* b_fc2    = (const float*)d_in[10];
    const float* w_fc3    = (const float*)d_in[11];
    const float* b_fc3    = (const float*)d_in[12];
    const float* w_mlp    = (const float*)d_in[13];
    const float* b_mlp    = (const float*)d_in[14];
    float* out = (float*)d_out;

    cudaFuncSetAttribute(prep_kernel, cudaFuncAttributeMaxDynamicSharedMemorySize, (16384 + 2048) * 4);
    cudaFuncSetAttribute(feat_kernel, cudaFuncAttributeMaxDynamicSharedMemorySize, 512 * 32 * 4);
    cudaFuncSetAttribute(pair_kernel, cudaFuncAttributeMaxDynamicSharedMemorySize, PAIR_SMEM_BYTES);

    prep_kernel<<<64, 256, (16384 + 2048) * 4>>>(w_conv1d, b_conv1d, w_c1,
                                                 x, w_mlp, b_mlp, out);
    feat_kernel<<<128, 320, 512 * 32 * 4>>>(x);
    pair_kernel<<<PAIR_BLOCKS, 512, PAIR_SMEM_BYTES>>>(b_c1, w_c2, b_c2, w_fc1, b_fc1,
                                                       w_fc2, b_fc2, w_fc3, b_fc3, out);
}

// round 5
// speedup vs baseline: 5.2216x; 1.1810x over previous
#include <cuda_runtime.h>
#include <math.h>

#define NSAMP 64
#define CIN   512
#define TT    64
#define NPAIR 2016
#define PAIR_BLOCKS 280
#define PAIR_SMEM_BYTES ((16384 + 8 * 4096) * 4)
#define PREP_SMEM_BYTES ((32 * 512 + 256 * 33) * 4)

typedef unsigned long long ull;

__device__ __forceinline__ ull pack2(float lo, float hi) {
    ull r;
    asm("mov.b64 %0, {%1, %2};" : "=l"(r) : "f"(lo), "f"(hi));
    return r;
}
__device__ __forceinline__ void unpack2(ull v, float &lo, float &hi) {
    asm("mov.b64 {%0, %1}, %2;" : "=f"(lo), "=f"(hi) : "l"(v));
}
__device__ __forceinline__ ull fma2(ull a, ull b, ull c) {
    ull d;
    asm("fma.rn.f32x2 %0, %1, %2, %3;" : "=l"(d) : "l"(a), "l"(b), "l"(c));
    return d;
}

// Scratch (device globals; no allocation allowed)
__device__ __align__(16) float g_Wt[512 * 320];          // [c][row]
__device__ __align__(16) float g_biasAll[320];
__device__ __align__(16) float g_Fe[NSAMP * 128 * 128];  // [n][t'][hw]
__device__ __align__(16) float g_G [NSAMP * 128 * 32];   // [n][t'][o]
__device__ __align__(16) float g_scorePart[NSAMP * 2];

// ---------------------------------------------------------------------------
// prep v2: 16 blocks, each owns 32 c' columns. Transposed fused weights + bias.
// ---------------------------------------------------------------------------
__global__ __launch_bounds__(256) void prep_kernel(const float* __restrict__ w_conv1d,
                            const float* __restrict__ b_conv1d,
                            const float* __restrict__ w_c1) {
    extern __shared__ float psm[];
    float* w1_sm = psm;                 // 32*512 = 16384
    float* wc_sm = psm + 16384;         // 256*33 padded
    int b = blockIdx.x;
    int tid = threadIdx.x;
    int c0 = b * 32;

    // stage w_c1 (64 KB)
    {
        const float4* src = (const float4*)w_c1;
        float4* dst = (float4*)w1_sm;
        #pragma unroll
        for (int k = 0; k < 16; ++k) dst[tid + k * 256] = src[tid + k * 256];
    }
    // stage w_conv slice [256 c][32 k] (padded rows) — coalesced 128B per row
    for (int idx = tid; idx < 2048; idx += 256) {
        int c = idx >> 3, k4 = idx & 7;
        float4 v = *(const float4*)(w_conv1d + c * 512 + c0 + k4 * 4);
        wc_sm[c * 33 + k4 * 4 + 0] = v.x;
        wc_sm[c * 33 + k4 * 4 + 1] = v.y;
        wc_sm[c * 33 + k4 * 4 + 2] = v.z;
        wc_sm[c * 33 + k4 * 4 + 3] = v.w;
    }
    __syncthreads();

    // transpose copy rows 0..255 -> g_Wt, contiguous in c per k
    for (int idx = tid; idx < 8192; idx += 256) {
        int k = idx >> 8, c = idx & 255;
        g_Wt[(c0 + k) * 320 + c] = wc_sm[c * 33 + k];
    }

    // fused A/B rows: 2 kinds x 32 o x 32 k = 2048 outputs
    for (int idx = tid; idx < 2048; idx += 256) {
        int kind = idx >> 10, o = (idx >> 5) & 31, k = idx & 31;
        float s0 = 0.f, s1 = 0.f;
        #pragma unroll 8
        for (int c = 0; c < 256; c += 2) {
            s0 += w1_sm[o * 512 + 2 * c + kind] * wc_sm[c * 33 + k];
            s1 += w1_sm[o * 512 + 2 * (c + 1) + kind] * wc_sm[(c + 1) * 33 + k];
        }
        g_Wt[(c0 + k) * 320 + 256 + kind * 32 + o] = s0 + s1;
    }

    if (b == 0) {
        if (tid < 256) g_biasAll[tid] = b_conv1d[tid];
        if (tid < 64) {
            int kind = tid >> 5, o = tid & 31;
            float s = 0.f;
            for (int c = 0; c < 256; ++c)
                s += w1_sm[o * 512 + 2 * c + kind] * b_conv1d[c];
            g_biasAll[256 + kind * 32 + o] = s;
        }
    }
}

// ---------------------------------------------------------------------------
// feat v3: 128 blocks = (n, t-half). 320 threads, tile 4 rows x 8 t.
// Weight prefetch depth 4. Also emits score partial dot (x . w_mlp) per half.
// ---------------------------------------------------------------------------
__global__ __launch_bounds__(320) void feat_kernel(const float* __restrict__ x,
                                                   const float* __restrict__ w_mlp) {
    extern __shared__ float x_sm[];                 // 512 x 32 = 64 KB
    __shared__ float red_sm[10];
    int bx = blockIdx.x;
    int n = bx >> 1, th = bx & 1;
    int tid = threadIdx.x;

    const float4* xg = (const float4*)(x + (size_t)n * CIN * TT);
    const float4* wg = (const float4*)w_mlp;
    float4* xs4 = (float4*)x_sm;
    float spart = 0.f;
    for (int idx = tid; idx < 4096; idx += 320) {
        int c = idx >> 3, k = idx & 7;
        float4 xv = xg[c * 16 + th * 8 + k];
        float4 wv = wg[c * 16 + th * 8 + k];
        xs4[idx] = xv;
        spart += xv.x * wv.x + xv.y * wv.y + xv.z * wv.z + xv.w * wv.w;
    }
    // warp reduce score partial
    #pragma unroll
    for (int off = 16; off > 0; off >>= 1)
        spart += __shfl_xor_sync(0xffffffffu, spart, off);
    if ((tid & 31) == 0) red_sm[tid >> 5] = spart;
    __syncthreads();
    if (tid == 0) {
        float t = 0.f;
        #pragma unroll
        for (int w = 0; w < 10; ++w) t += red_sm[w];
        g_scorePart[n * 2 + th] = t;
    }

    int rq = tid >> 2, tg = tid & 3;
    int row0 = rq * 4, t0l = tg * 8;

    ull acc[4][4];
    #pragma unroll
    for (int r = 0; r < 4; ++r)
        #pragma unroll
        for (int k = 0; k < 4; ++k) acc[r][k] = 0ULL;

    // prefetch depth 4 on weight rows
    float4 wbuf[4];
    #pragma unroll
    for (int d = 0; d < 4; ++d)
        wbuf[d] = *(const float4*)(g_Wt + d * 320 + row0);

    for (int cb = 0; cb < 512; cb += 4) {
        float4 wno[4];
        #pragma unroll
        for (int d = 0; d < 4; ++d) wno[d] = wbuf[d];
        if (cb + 4 < 512) {
            #pragma unroll
            for (int d = 0; d < 4; ++d)
                wbuf[d] = *(const float4*)(g_Wt + (cb + 4 + d) * 320 + row0);
        }
        #pragma unroll
        for (int d = 0; d < 4; ++d) {
            int c = cb + d;
            const ulonglong2* xp = (const ulonglong2*)(x_sm + c * 32 + t0l);
            ulonglong2 xa = xp[0], xb = xp[1];
            float wa[4] = {wno[d].x, wno[d].y, wno[d].z, wno[d].w};
            #pragma unroll
            for (int r = 0; r < 4; ++r) {
                ull wp = pack2(wa[r], wa[r]);
                acc[r][0] = fma2(wp, xa.x, acc[r][0]);
                acc[r][1] = fma2(wp, xa.y, acc[r][1]);
                acc[r][2] = fma2(wp, xb.x, acc[r][2]);
                acc[r][3] = fma2(wp, xb.y, acc[r][3]);
            }
        }
    }

    #pragma unroll
    for (int r = 0; r < 4; ++r) {
        int row = row0 + r;
        float bias = g_biasAll[row];
        float v[8];
        unpack2(acc[r][0], v[0], v[1]);
        unpack2(acc[r][1], v[2], v[3]);
        unpack2(acc[r][2], v[4], v[5]);
        unpack2(acc[r][3], v[6], v[7]);
        #pragma unroll
        for (int k = 0; k < 8; ++k) {
            float val = v[k] + bias;
            int t = th * 32 + t0l + k;
            if (row < 256) {
                int d = row;
                int tp = (d < 128) ? t : (64 + t);
                int hw = d & 127;
                g_Fe[(size_t)n * 16384 + tp * 128 + hw] = val;
            } else if (row < 288) {
                g_G[(size_t)n * 4096 + t * 32 + (row - 256)] = val;
            } else {
                g_G[(size_t)n * 4096 + (64 + t) * 32 + (row - 288)] = val;
            }
        }
    }
}

// ---------------------------------------------------------------------------
// pair: 280 blocks grouped by j, 8 i-units each. 512 thr = 8 units x 64.
// Also finalizes score sigmoid on blocks 0..63.
// ---------------------------------------------------------------------------
__global__ __launch_bounds__(512) void pair_kernel(const float* __restrict__ b_c1,
                            const float* __restrict__ w_c2, const float* __restrict__ b_c2,
                            const float* __restrict__ w_fc1, const float* __restrict__ b_fc1,
                            const float* __restrict__ w_fc2, const float* __restrict__ b_fc2,
                            const float* __restrict__ w_fc3, const float* __restrict__ b_fc3,
                            const float* __restrict__ b_mlp,
                            float* __restrict__ out) {
    extern __shared__ float sm[];
    float* fe_sm = sm;                       // [128][128]

    int tid = threadIdx.x;
    int b = blockIdx.x;

    // score finalize (independent, cheap)
    if (b < NSAMP && tid == 480) {
        float z = g_scorePart[2 * b] + g_scorePart[2 * b + 1] + b_mlp[0];
        out[b] = 1.f / (1.f + expf(-z));
    }

    int j = 1;
    while (b >= ((j + 7) >> 3)) { b -= (j + 7) >> 3; ++j; }
    int i0 = b * 8;

    int u = tid >> 6, t64 = tid & 63;
    int og = t64 >> 4, hg = t64 & 15;
    float* Gu = sm + 16384 + u * 4096;       // [128][32] per unit

    {
        const float4* fg = (const float4*)(g_Fe + (size_t)j * 16384);
        float4* fs = (float4*)fe_sm;
        #pragma unroll
        for (int k = 0; k < 8; ++k) fs[tid + k * 512] = fg[tid + k * 512];
        int iu = i0 + u; if (iu >= j) iu = j - 1;
        const float4* gg = (const float4*)(g_G + (size_t)iu * 4096);
        float4* gs = (float4*)Gu;
        #pragma unroll
        for (int k = 0; k < 16; ++k) gs[t64 + k * 64] = gg[t64 + k * 64];
    }
    __syncthreads();

    int o0 = og * 8, hw0 = hg * 8;
    ull acc[8][4];
    #pragma unroll
    for (int oo = 0; oo < 8; ++oo)
        #pragma unroll
        for (int k = 0; k < 4; ++k) acc[oo][k] = 0ULL;

    #pragma unroll 2
    for (int t = 0; t < 128; ++t) {
        float4 af0 = *(const float4*)(Gu + t * 32 + o0);
        float4 af1 = *(const float4*)(Gu + t * 32 + o0 + 4);
        const ulonglong2* fp = (const ulonglong2*)(fe_sm + t * 128 + hw0);
        ulonglong2 fA = fp[0], fB = fp[1];
        float av[8] = {af0.x, af0.y, af0.z, af0.w, af1.x, af1.y, af1.z, af1.w};
        #pragma unroll
        for (int oo = 0; oo < 8; ++oo) {
            ull ap = pack2(av[oo], av[oo]);
            acc[oo][0] = fma2(ap, fA.x, acc[oo][0]);
            acc[oo][1] = fma2(ap, fA.y, acc[oo][1]);
            acc[oo][2] = fma2(ap, fB.x, acc[oo][2]);
            acc[oo][3] = fma2(ap, fB.y, acc[oo][3]);
        }
    }

    bool valid = (i0 + u) < j;
    int bar = u + 1;

    float* pool = Gu;           // [32 s][33]
    float* g2   = Gu + 1056;    // [8][32]
    float* vv   = Gu + 1312;    // 64
    float* v1   = Gu + 1376;    // 32
    float* v2   = Gu + 1408;    // 8

    asm volatile("bar.sync %0, 64;" :: "r"(bar));

    #pragma unroll
    for (int oo = 0; oo < 8; ++oo) {
        int o = o0 + oo;
        float bb = b_c1[o];
        float v0, v1f, v2f, v3, v4, v5, v6, v7;
        unpack2(acc[oo][0], v0, v1f);
        unpack2(acc[oo][1], v2f, v3);
        unpack2(acc[oo][2], v4, v5);
        unpack2(acc[oo][3], v6, v7);
        float q0 = fmaxf(fmaxf(v0, v1f), fmaxf(v4, v5)) + bb;
        float q1 = fmaxf(fmaxf(v2f, v3), fmaxf(v6, v7)) + bb;
        pool[(2 * hg + 0) * 33 + o] = q0;
        pool[(2 * hg + 1) * 33 + o] = q1;
    }
    asm volatile("bar.sync %0, 64;" :: "r"(bar));

    #pragma unroll
    for (int k = 0; k < 4; ++k) {
        int idx = t64 + k * 64;
        int o2 = idx >> 5, s = idx & 31;
        float sum = b_c2[o2];
        const float* wr = w_c2 + o2 * 32;
        #pragma unroll
        for (int oo = 0; oo < 32; ++oo)
            sum += wr[oo] * pool[s * 33 + oo];
        g2[o2 * 32 + s] = sum;
    }
    asm volatile("bar.sync %0, 64;" :: "r"(bar));

    {
        int o2 = t64 >> 3, q = t64 & 7;
        const float* gb = g2 + o2 * 32 + q * 4;
        vv[t64] = fmaxf(fmaxf(gb[0], gb[1]), fmaxf(gb[2], gb[3]));
    }
    asm volatile("bar.sync %0, 64;" :: "r"(bar));

    if (t64 < 32) {
        float z = b_fc1[t64];
        #pragma unroll
        for (int m = 0; m < 64; ++m) z += w_fc1[t64 * 64 + m] * vv[m];
        v1[t64] = fmaxf(z, 0.f);
    }
    asm volatile("bar.sync %0, 64;" :: "r"(bar));
    if (t64 < 8) {
        float z = b_fc2[t64];
        #pragma unroll
        for (int m = 0; m < 32; ++m) z += w_fc2[t64 * 32 + m] * v1[m];
        v2[t64] = fmaxf(z, 0.f);
    }
    asm volatile("bar.sync %0, 64;" :: "r"(bar));
    if (t64 == 0 && valid) {
        float z = b_fc3[0];
        #pragma unroll
        for (int m = 0; m < 8; ++m) z += w_fc3[m] * v2[m];
        int i = i0 + u;
        int p = i * (2 * NSAMP - i - 1) / 2 + (j - i - 1);
        out[NSAMP + p] = 1.f / (1.f + expf(-z));
    }
}

extern "C" void kernel_launch(void* const* d_in, const int* in_sizes, int n_in,
                              void* d_out, int out_size) {
    const float* x        = (const float*)d_in[0];
    const float* w_conv1d = (const float*)d_in[1];
    const float* b_conv1d = (const float*)d_in[2];
    const float* w_c1     = (const float*)d_in[3];
    const float* b_c1     = (const float*)d_in[4];
    const float* w_c2     = (const float*)d_in[5];
    const float* b_c2     = (const float*)d_in[6];
    const float* w_fc1    = (const float*)d_in[7];
    const float* b_fc1    = (const float*)d_in[8];
    const float* w_fc2    = (const float*)d_in[9];
    const float* b_fc2    = (const float*)d_in[10];
    const float* w_fc3    = (const float*)d_in[11];
    const float* b_fc3    = (const float*)d_in[12];
    const float* w_mlp    = (const float*)d_in[13];
    const float* b_mlp    = (const float*)d_in[14];
    float* out = (float*)d_out;

    cudaFuncSetAttribute(prep_kernel, cudaFuncAttributeMaxDynamicSharedMemorySize, PREP_SMEM_BYTES);
    cudaFuncSetAttribute(feat_kernel, cudaFuncAttributeMaxDynamicSharedMemorySize, 512 * 32 * 4);
    cudaFuncSetAttribute(pair_kernel, cudaFuncAttributeMaxDynamicSharedMemorySize, PAIR_SMEM_BYTES);

    prep_kernel<<<16, 256, PREP_SMEM_BYTES>>>(w_conv1d, b_conv1d, w_c1);
    feat_kernel<<<128, 320, 512 * 32 * 4>>>(x, w_mlp);
    pair_kernel<<<PAIR_BLOCKS, 512, PAIR_SMEM_BYTES>>>(b_c1, w_c2, b_c2, w_fc1, b_fc1,
                                                       w_fc2, b_fc2, w_fc3, b_fc3, b_mlp, out);
}

// round 6
// speedup vs baseline: 6.2015x; 1.1877x over previous
#include <cuda_runtime.h>
#include <math.h>

#define NSAMP 64
#define CIN   512
#define TT    64
#define NPAIR 2016
#define PAIR_BLOCKS 280
#define PAIR_SMEM_BYTES ((16384 + 8 * 4096) * 4)
#define PREP_SMEM_BYTES ((32 * 512 + 256 * 17 + 256) * 4)

typedef unsigned long long ull;

__device__ __forceinline__ ull pack2(float lo, float hi) {
    ull r;
    asm("mov.b64 %0, {%1, %2};" : "=l"(r) : "f"(lo), "f"(hi));
    return r;
}
__device__ __forceinline__ void unpack2(ull v, float &lo, float &hi) {
    asm("mov.b64 {%0, %1}, %2;" : "=f"(lo), "=f"(hi) : "l"(v));
}
__device__ __forceinline__ ull fma2(ull a, ull b, ull c) {
    ull d;
    asm("fma.rn.f32x2 %0, %1, %2, %3;" : "=l"(d) : "l"(a), "l"(b), "l"(c));
    return d;
}

// Scratch (device globals; no allocation allowed)
__device__ __align__(16) float g_Wt[512 * 320];          // [c][row]
__device__ __align__(16) float g_biasAll[320];
__device__ __align__(16) float g_Fe[NSAMP * 128 * 128];  // [n][t'][hw]
__device__ __align__(16) float g_G [NSAMP * 128 * 32];   // [n][t'][o]
__device__ __align__(16) float g_scorePart[NSAMP * 2];

// ---------------------------------------------------------------------------
// prep v3: 32 blocks x 16 c' columns. Fused-register A/B, parallel bias.
// ---------------------------------------------------------------------------
__global__ __launch_bounds__(256) void prep_kernel(const float* __restrict__ w_conv1d,
                            const float* __restrict__ b_conv1d,
                            const float* __restrict__ w_c1) {
    extern __shared__ float psm[];
    float* w1_sm = psm;                     // 32*512 = 16384
    float* wc_sm = psm + 16384;             // 256 x 17 (pad) = 4352
    float* b_sm  = psm + 16384 + 4352;      // 256
    int b = blockIdx.x;
    int tid = threadIdx.x;
    int c0 = b * 16;

    // stage w_c1 (64 KB)
    {
        const float4* src = (const float4*)w_c1;
        float4* dst = (float4*)w1_sm;
        #pragma unroll
        for (int k = 0; k < 16; ++k) dst[tid + k * 256] = src[tid + k * 256];
    }
    // stage w_conv slice [256 c][16 k] into padded smem
    for (int idx = tid; idx < 1024; idx += 256) {
        int c = idx >> 2, k4 = idx & 3;
        float4 v = *(const float4*)(w_conv1d + c * 512 + c0 + k4 * 4);
        wc_sm[c * 17 + k4 * 4 + 0] = v.x;
        wc_sm[c * 17 + k4 * 4 + 1] = v.y;
        wc_sm[c * 17 + k4 * 4 + 2] = v.z;
        wc_sm[c * 17 + k4 * 4 + 3] = v.w;
    }
    if (b == 0) b_sm[tid] = b_conv1d[tid];
    __syncthreads();

    // transpose copy rows 0..255 -> g_Wt (LDS stride-17 conflict-free, STG coalesced)
    for (int idx = tid; idx < 4096; idx += 256) {
        int k = idx >> 8, c = idx & 255;
        g_Wt[(c0 + k) * 320 + c] = wc_sm[c * 17 + k];
    }

    // fused A/B: thread = (k = tid&15, oq = tid>>4); o = oq*2 + r; kinds packed in fma2 lanes
    {
        int k = tid & 15, oq = tid >> 4;
        int o0 = oq * 2;
        const ull* w1p0 = (const ull*)(w1_sm + (o0 + 0) * 512);
        const ull* w1p1 = (const ull*)(w1_sm + (o0 + 1) * 512);
        ull acc0 = 0ULL, acc1 = 0ULL;
        #pragma unroll 8
        for (int c = 0; c < 256; ++c) {
            float wcv = wc_sm[c * 17 + k];
            ull wcd = pack2(wcv, wcv);
            acc0 = fma2(w1p0[c], wcd, acc0);
            acc1 = fma2(w1p1[c], wcd, acc1);
        }
        float a0lo, a0hi, a1lo, a1hi;
        unpack2(acc0, a0lo, a0hi);
        unpack2(acc1, a1lo, a1hi);
        float* dst = g_Wt + (c0 + k) * 320 + 256;
        dst[o0 + 0]      = a0lo;   // kind 0
        dst[32 + o0 + 0] = a0hi;   // kind 1
        dst[o0 + 1]      = a1lo;
        dst[32 + o0 + 1] = a1hi;
    }

    // parallel bias (block 0): warp-per-8-outputs with shfl reduce
    if (b == 0) {
        int wid = tid >> 5, lane = tid & 31;
        #pragma unroll
        for (int s = 0; s < 8; ++s) {
            int row = wid * 8 + s;          // 0..63
            int kind = row >> 5, o = row & 31;
            float p = 0.f;
            #pragma unroll
            for (int cc = 0; cc < 8; ++cc) {
                int c = lane + 32 * cc;
                p += w1_sm[o * 512 + 2 * c + kind] * b_sm[c];
            }
            #pragma unroll
            for (int off = 16; off > 0; off >>= 1)
                p += __shfl_xor_sync(0xffffffffu, p, off);
            if (lane == 0) g_biasAll[256 + kind * 32 + o] = p;
        }
        g_biasAll[tid] = b_sm[tid];
    }
}

// ---------------------------------------------------------------------------
// feat: 128 blocks = (n, t-half). 320 threads, tile 4 rows x 8 t.
// Weight prefetch depth 4. Emits score partial dot per half.
// ---------------------------------------------------------------------------
__global__ __launch_bounds__(320) void feat_kernel(const float* __restrict__ x,
                                                   const float* __restrict__ w_mlp) {
    extern __shared__ float x_sm[];                 // 512 x 32 = 64 KB
    __shared__ float red_sm[10];
    int bx = blockIdx.x;
    int n = bx >> 1, th = bx & 1;
    int tid = threadIdx.x;

    const float4* xg = (const float4*)(x + (size_t)n * CIN * TT);
    const float4* wg = (const float4*)w_mlp;
    float4* xs4 = (float4*)x_sm;
    float spart = 0.f;
    for (int idx = tid; idx < 4096; idx += 320) {
        int c = idx >> 3, k = idx & 7;
        float4 xv = xg[c * 16 + th * 8 + k];
        float4 wv = wg[c * 16 + th * 8 + k];
        xs4[idx] = xv;
        spart += xv.x * wv.x + xv.y * wv.y + xv.z * wv.z + xv.w * wv.w;
    }
    #pragma unroll
    for (int off = 16; off > 0; off >>= 1)
        spart += __shfl_xor_sync(0xffffffffu, spart, off);
    if ((tid & 31) == 0) red_sm[tid >> 5] = spart;
    __syncthreads();
    if (tid == 0) {
        float t = 0.f;
        #pragma unroll
        for (int w = 0; w < 10; ++w) t += red_sm[w];
        g_scorePart[n * 2 + th] = t;
    }

    int rq = tid >> 2, tg = tid & 3;
    int row0 = rq * 4, t0l = tg * 8;

    ull acc[4][4];
    #pragma unroll
    for (int r = 0; r < 4; ++r)
        #pragma unroll
        for (int k = 0; k < 4; ++k) acc[r][k] = 0ULL;

    float4 wbuf[4];
    #pragma unroll
    for (int d = 0; d < 4; ++d)
        wbuf[d] = *(const float4*)(g_Wt + d * 320 + row0);

    for (int cb = 0; cb < 512; cb += 4) {
        float4 wno[4];
        #pragma unroll
        for (int d = 0; d < 4; ++d) wno[d] = wbuf[d];
        if (cb + 4 < 512) {
            #pragma unroll
            for (int d = 0; d < 4; ++d)
                wbuf[d] = *(const float4*)(g_Wt + (cb + 4 + d) * 320 + row0);
        }
        #pragma unroll
        for (int d = 0; d < 4; ++d) {
            int c = cb + d;
            const ulonglong2* xp = (const ulonglong2*)(x_sm + c * 32 + t0l);
            ulonglong2 xa = xp[0], xb = xp[1];
            float wa[4] = {wno[d].x, wno[d].y, wno[d].z, wno[d].w};
            #pragma unroll
            for (int r = 0; r < 4; ++r) {
                ull wp = pack2(wa[r], wa[r]);
                acc[r][0] = fma2(wp, xa.x, acc[r][0]);
                acc[r][1] = fma2(wp, xa.y, acc[r][1]);
                acc[r][2] = fma2(wp, xb.x, acc[r][2]);
                acc[r][3] = fma2(wp, xb.y, acc[r][3]);
            }
        }
    }

    #pragma unroll
    for (int r = 0; r < 4; ++r) {
        int row = row0 + r;
        float bias = g_biasAll[row];
        float v[8];
        unpack2(acc[r][0], v[0], v[1]);
        unpack2(acc[r][1], v[2], v[3]);
        unpack2(acc[r][2], v[4], v[5]);
        unpack2(acc[r][3], v[6], v[7]);
        #pragma unroll
        for (int k = 0; k < 8; ++k) {
            float val = v[k] + bias;
            int t = th * 32 + t0l + k;
            if (row < 256) {
                int d = row;
                int tp = (d < 128) ? t : (64 + t);
                int hw = d & 127;
                g_Fe[(size_t)n * 16384 + tp * 128 + hw] = val;
            } else if (row < 288) {
                g_G[(size_t)n * 4096 + t * 32 + (row - 256)] = val;
            } else {
                g_G[(size_t)n * 4096 + (64 + t) * 32 + (row - 288)] = val;
            }
        }
    }
}

// ---------------------------------------------------------------------------
// pair: 280 blocks grouped by j, 8 i-units each. 512 thr = 8 units x 64.
// Also finalizes score sigmoid on blocks 0..63.
// ---------------------------------------------------------------------------
__global__ __launch_bounds__(512) void pair_kernel(const float* __restrict__ b_c1,
                            const float* __restrict__ w_c2, const float* __restrict__ b_c2,
                            const float* __restrict__ w_fc1, const float* __restrict__ b_fc1,
                            const float* __restrict__ w_fc2, const float* __restrict__ b_fc2,
                            const float* __restrict__ w_fc3, const float* __restrict__ b_fc3,
                            const float* __restrict__ b_mlp,
                            float* __restrict__ out) {
    extern __shared__ float sm[];
    float* fe_sm = sm;                       // [128][128]

    int tid = threadIdx.x;
    int b = blockIdx.x;

    if (b < NSAMP && tid == 480) {
        float z = g_scorePart[2 * b] + g_scorePart[2 * b + 1] + b_mlp[0];
        out[b] = 1.f / (1.f + expf(-z));
    }

    int j = 1;
    while (b >= ((j + 7) >> 3)) { b -= (j + 7) >> 3; ++j; }
    int i0 = b * 8;

    int u = tid >> 6, t64 = tid & 63;
    int og = t64 >> 4, hg = t64 & 15;
    float* Gu = sm + 16384 + u * 4096;       // [128][32] per unit

    {
        const float4* fg = (const float4*)(g_Fe + (size_t)j * 16384);
        float4* fs = (float4*)fe_sm;
        #pragma unroll
        for (int k = 0; k < 8; ++k) fs[tid + k * 512] = fg[tid + k * 512];
        int iu = i0 + u; if (iu >= j) iu = j - 1;
        const float4* gg = (const float4*)(g_G + (size_t)iu * 4096);
        float4* gs = (float4*)Gu;
        #pragma unroll
        for (int k = 0; k < 16; ++k) gs[t64 + k * 64] = gg[t64 + k * 64];
    }
    __syncthreads();

    int o0 = og * 8, hw0 = hg * 8;
    ull acc[8][4];
    #pragma unroll
    for (int oo = 0; oo < 8; ++oo)
        #pragma unroll
        for (int k = 0; k < 4; ++k) acc[oo][k] = 0ULL;

    #pragma unroll 2
    for (int t = 0; t < 128; ++t) {
        float4 af0 = *(const float4*)(Gu + t * 32 + o0);
        float4 af1 = *(const float4*)(Gu + t * 32 + o0 + 4);
        const ulonglong2* fp = (const ulonglong2*)(fe_sm + t * 128 + hw0);
        ulonglong2 fA = fp[0], fB = fp[1];
        float av[8] = {af0.x, af0.y, af0.z, af0.w, af1.x, af1.y, af1.z, af1.w};
        #pragma unroll
        for (int oo = 0; oo < 8; ++oo) {
            ull ap = pack2(av[oo], av[oo]);
            acc[oo][0] = fma2(ap, fA.x, acc[oo][0]);
            acc[oo][1] = fma2(ap, fA.y, acc[oo][1]);
            acc[oo][2] = fma2(ap, fB.x, acc[oo][2]);
            acc[oo][3] = fma2(ap, fB.y, acc[oo][3]);
        }
    }

    bool valid = (i0 + u) < j;
    int bar = u + 1;

    float* pool = Gu;           // [32 s][33]
    float* g2   = Gu + 1056;    // [8][32]
    float* vv   = Gu + 1312;    // 64
    float* v1   = Gu + 1376;    // 32
    float* v2   = Gu + 1408;    // 8

    asm volatile("bar.sync %0, 64;" :: "r"(bar));

    #pragma unroll
    for (int oo = 0; oo < 8; ++oo) {
        int o = o0 + oo;
        float bb = b_c1[o];
        float v0, v1f, v2f, v3, v4, v5, v6, v7;
        unpack2(acc[oo][0], v0, v1f);
        unpack2(acc[oo][1], v2f, v3);
        unpack2(acc[oo][2], v4, v5);
        unpack2(acc[oo][3], v6, v7);
        float q0 = fmaxf(fmaxf(v0, v1f), fmaxf(v4, v5)) + bb;
        float q1 = fmaxf(fmaxf(v2f, v3), fmaxf(v6, v7)) + bb;
        pool[(2 * hg + 0) * 33 + o] = q0;
        pool[(2 * hg + 1) * 33 + o] = q1;
    }
    asm volatile("bar.sync %0, 64;" :: "r"(bar));

    #pragma unroll
    for (int k = 0; k < 4; ++k) {
        int idx = t64 + k * 64;
        int o2 = idx >> 5, s = idx & 31;
        float sum = b_c2[o2];
        const float* wr = w_c2 + o2 * 32;
        #pragma unroll
        for (int oo = 0; oo < 32; ++oo)
            sum += wr[oo] * pool[s * 33 + oo];
        g2[o2 * 32 + s] = sum;
    }
    asm volatile("bar.sync %0, 64;" :: "r"(bar));

    {
        int o2 = t64 >> 3, q = t64 & 7;
        const float* gb = g2 + o2 * 32 + q * 4;
        vv[t64] = fmaxf(fmaxf(gb[0], gb[1]), fmaxf(gb[2], gb[3]));
    }
    asm volatile("bar.sync %0, 64;" :: "r"(bar));

    if (t64 < 32) {
        float z = b_fc1[t64];
        #pragma unroll
        for (int m = 0; m < 64; ++m) z += w_fc1[t64 * 64 + m] * vv[m];
        v1[t64] = fmaxf(z, 0.f);
    }
    asm volatile("bar.sync %0, 64;" :: "r"(bar));
    if (t64 < 8) {
        float z = b_fc2[t64];
        #pragma unroll
        for (int m = 0; m < 32; ++m) z += w_fc2[t64 * 32 + m] * v1[m];
        v2[t64] = fmaxf(z, 0.f);
    }
    asm volatile("bar.sync %0, 64;" :: "r"(bar));
    if (t64 == 0 && valid) {
        float z = b_fc3[0];
        #pragma unroll
        for (int m = 0; m < 8; ++m) z += w_fc3[m] * v2[m];
        int i = i0 + u;
        int p = i * (2 * NSAMP - i - 1) / 2 + (j - i - 1);
        out[NSAMP + p] = 1.f / (1.f + expf(-z));
    }
}

extern "C" void kernel_launch(void* const* d_in, const int* in_sizes, int n_in,
                              void* d_out, int out_size) {
    const float* x        = (const float*)d_in[0];
    const float* w_conv1d = (const float*)d_in[1];
    const float* b_conv1d = (const float*)d_in[2];
    const float* w_c1     = (const float*)d_in[3];
    const float* b_c1     = (const float*)d_in[4];
    const float* w_c2     = (const float*)d_in[5];
    const float* b_c2     = (const float*)d_in[6];
    const float* w_fc1    = (const float*)d_in[7];
    const float* b_fc1    = (const float*)d_in[8];
    const float* w_fc2    = (const float*)d_in[9];
    const float* b_fc2    = (const float*)d_in[10];
    const float* w_fc3    = (const float*)d_in[11];
    const float* b_fc3    = (const float*)d_in[12];
    const float* w_mlp    = (const float*)d_in[13];
    const float* b_mlp    = (const float*)d_in[14];
    float* out = (float*)d_out;

    cudaFuncSetAttribute(prep_kernel, cudaFuncAttributeMaxDynamicSharedMemorySize, PREP_SMEM_BYTES);
    cudaFuncSetAttribute(feat_kernel, cudaFuncAttributeMaxDynamicSharedMemorySize, 512 * 32 * 4);
    cudaFuncSetAttribute(pair_kernel, cudaFuncAttributeMaxDynamicSharedMemorySize, PAIR_SMEM_BYTES);

    prep_kernel<<<32, 256, PREP_SMEM_BYTES>>>(w_conv1d, b_conv1d, w_c1);
    feat_kernel<<<128, 320, 512 * 32 * 4>>>(x, w_mlp);
    pair_kernel<<<PAIR_BLOCKS, 512, PAIR_SMEM_BYTES>>>(b_c1, w_c2, b_c2, w_fc1, b_fc1,
                                                       w_fc2, b_fc2, w_fc3, b_fc3, b_mlp, out);
}